// round 1
// baseline (speedup 1.0000x reference)
#include <cuda_runtime.h>
#include <cstdint>

// Problem constants (fixed-shape problem)
constexpr int BSZ = 8192;
constexpr int HH  = 2048;
constexpr int DD  = 104;
#define SKEW 20   // smem row stride in floats: conflict-free for mma fragment loads

static __device__ __forceinline__ unsigned f2u(float x) { return __float_as_uint(x); }

static __device__ __forceinline__ float tf32r(float x) {
    unsigned u;
    asm("cvt.rna.tf32.f32 %0, %1;" : "=r"(u) : "f"(x));
    return __uint_as_float(u);
}

static __device__ __forceinline__ void mma8(float c[4], const unsigned a[4], const unsigned b[2]) {
    asm volatile(
        "mma.sync.aligned.m16n8k8.row.col.f32.tf32.tf32.f32 "
        "{%0,%1,%2,%3}, {%4,%5,%6,%7}, {%8,%9}, {%0,%1,%2,%3};\n"
        : "+f"(c[0]), "+f"(c[1]), "+f"(c[2]), "+f"(c[3])
        : "r"(a[0]), "r"(a[1]), "r"(a[2]), "r"(a[3]), "r"(b[0]), "r"(b[1]));
}

static __device__ __forceinline__ float sigmoidf_(float x) {
    return 1.0f / (1.0f + __expf(-x));
}

// ============================================================================
// Kernel 1: h_t = sigmoid(hidden @ U_w^T + line @ W_w^T + U_b + W_b)
// Tiles: 128x128, BK=16, 256 threads (2x4 warp grid, 64x32 warp tiles),
// double-buffered smem, tf32 mma. K phases: 2048 (hidden/U_w) then 104 (line/W_w).
// ============================================================================
__global__ __launch_bounds__(256) void rnn_k1(
    const float* __restrict__ hidden, const float* __restrict__ line,
    const float* __restrict__ U_w,    const float* __restrict__ W_w,
    const float* __restrict__ U_b,    const float* __restrict__ W_b,
    float* __restrict__ ht)
{
    __shared__ float As[2][128][SKEW];
    __shared__ float Bs[2][128][SKEW];

    const int tid  = threadIdx.x;
    const int warp = tid >> 5, lane = tid & 31;
    const int wm   = (warp >> 2) * 64;   // warp M offset: 0 or 64
    const int wn   = (warp & 3) * 32;    // warp N offset: 0,32,64,96
    const int grp  = lane >> 2, tig = lane & 3;

    const int mBase = blockIdx.y * 128;
    const int nBase = blockIdx.x * 128;

    const float* A1 = hidden + (size_t)mBase * HH;
    const float* B1 = U_w    + (size_t)nBase * HH;
    const float* A2 = line   + (size_t)mBase * DD;
    const float* B2 = W_w    + (size_t)nBase * DD;

    // loader mapping: 512 float4 per operand tile, 2 per thread
    const int lr = tid >> 2;            // row 0..63, +64 for second
    const int lc = (tid & 3) * 4;       // col 0,4,8,12

    float acc[4][4][4];
    #pragma unroll
    for (int i = 0; i < 4; i++)
        #pragma unroll
        for (int j = 0; j < 4; j++)
            #pragma unroll
            for (int k = 0; k < 4; k++) acc[i][j][k] = 0.f;

    // --- load tile 0 (phase A, always fully valid) ---
    #pragma unroll
    for (int i = 0; i < 2; i++) {
        int r = lr + i * 64;
        float4 va = *(const float4*)(A1 + (size_t)r * HH + lc);
        float4 vb = *(const float4*)(B1 + (size_t)r * HH + lc);
        float4 wa = make_float4(tf32r(va.x), tf32r(va.y), tf32r(va.z), tf32r(va.w));
        float4 wb = make_float4(tf32r(vb.x), tf32r(vb.y), tf32r(vb.z), tf32r(vb.w));
        *(float4*)&As[0][r][lc] = wa;
        *(float4*)&Bs[0][r][lc] = wb;
    }
    __syncthreads();

    const int NT1 = HH / 16;            // 128 tiles, phase A
    const int NT  = NT1 + (DD + 15) / 16; // +7 tiles, phase B
    int buf = 0;

    for (int t = 0; t < NT; t++) {
        float4 ra[2], rb[2];
        if (t + 1 < NT) {
            int tn = t + 1;
            const float *aP, *bP; int lda, k0, kmax;
            if (tn < NT1) { aP = A1; bP = B1; lda = HH; k0 = tn * 16;        kmax = HH; }
            else          { aP = A2; bP = B2; lda = DD; k0 = (tn - NT1) * 16; kmax = DD; }
            const bool v = (k0 + lc) < kmax;   // DD%4==0 so float4 granularity is safe
            #pragma unroll
            for (int i = 0; i < 2; i++) {
                int r = lr + i * 64;
                ra[i] = v ? *(const float4*)(aP + (size_t)r * lda + k0 + lc)
                          : make_float4(0.f, 0.f, 0.f, 0.f);
                rb[i] = v ? *(const float4*)(bP + (size_t)r * lda + k0 + lc)
                          : make_float4(0.f, 0.f, 0.f, 0.f);
            }
        }

        // --- compute current buffer ---
        const float (*Ac)[SKEW] = As[buf];
        const float (*Bc)[SKEW] = Bs[buf];
        #pragma unroll
        for (int kk = 0; kk < 16; kk += 8) {
            unsigned a[4][4], b[4][2];
            #pragma unroll
            for (int mt = 0; mt < 4; mt++) {
                int r0 = wm + mt * 16 + grp;
                a[mt][0] = f2u(Ac[r0    ][kk + tig    ]);
                a[mt][1] = f2u(Ac[r0 + 8][kk + tig    ]);
                a[mt][2] = f2u(Ac[r0    ][kk + tig + 4]);
                a[mt][3] = f2u(Ac[r0 + 8][kk + tig + 4]);
            }
            #pragma unroll
            for (int nt = 0; nt < 4; nt++) {
                int c0 = wn + nt * 8 + grp;
                b[nt][0] = f2u(Bc[c0][kk + tig    ]);
                b[nt][1] = f2u(Bc[c0][kk + tig + 4]);
            }
            #pragma unroll
            for (int mt = 0; mt < 4; mt++)
                #pragma unroll
                for (int nt = 0; nt < 4; nt++)
                    mma8(acc[mt][nt], a[mt], b[nt]);
        }

        if (t + 1 < NT) {
            float (*An)[SKEW] = As[buf ^ 1];
            float (*Bn)[SKEW] = Bs[buf ^ 1];
            #pragma unroll
            for (int i = 0; i < 2; i++) {
                int r = lr + i * 64;
                *(float4*)&An[r][lc] = make_float4(tf32r(ra[i].x), tf32r(ra[i].y),
                                                   tf32r(ra[i].z), tf32r(ra[i].w));
                *(float4*)&Bn[r][lc] = make_float4(tf32r(rb[i].x), tf32r(rb[i].y),
                                                   tf32r(rb[i].z), tf32r(rb[i].w));
            }
            __syncthreads();
            buf ^= 1;
        }
    }

    // --- epilogue: bias + sigmoid, write h_t ---
    #pragma unroll
    for (int nt = 0; nt < 4; nt++) {
        int cn = nBase + wn + nt * 8 + tig * 2;
        float b0 = U_b[cn]     + W_b[cn];
        float b1 = U_b[cn + 1] + W_b[cn + 1];
        #pragma unroll
        for (int mt = 0; mt < 4; mt++) {
            int rm = mBase + wm + mt * 16 + grp;
            float2 o0 = make_float2(sigmoidf_(acc[mt][nt][0] + b0),
                                    sigmoidf_(acc[mt][nt][1] + b1));
            float2 o1 = make_float2(sigmoidf_(acc[mt][nt][2] + b0),
                                    sigmoidf_(acc[mt][nt][3] + b1));
            *(float2*)&ht[(size_t)rm * HH + cn]       = o0;
            *(float2*)&ht[(size_t)(rm + 8) * HH + cn] = o1;
        }
    }
}

// ============================================================================
// Kernel 2: pred = h_t @ V_w^T + V_b   [8192 x 104]
// Tiles: 64x104, BK=16, 128 threads (4 warps, warp tile 16x104), double-buffered.
// ============================================================================
__global__ __launch_bounds__(128) void rnn_k2(
    const float* __restrict__ ht, const float* __restrict__ V_w,
    const float* __restrict__ V_b, float* __restrict__ pred)
{
    __shared__ float As[2][64][SKEW];
    __shared__ float Bs[2][104][SKEW];

    const int tid  = threadIdx.x;
    const int warp = tid >> 5, lane = tid & 31;
    const int wm   = warp * 16;
    const int grp  = lane >> 2, tig = lane & 3;

    const int mBase = blockIdx.x * 64;
    const float* Ap = ht + (size_t)mBase * HH;

    const int lr = tid >> 2;       // 0..31
    const int lc = (tid & 3) * 4;

    float acc[13][4];
    #pragma unroll
    for (int i = 0; i < 13; i++)
        #pragma unroll
        for (int j = 0; j < 4; j++) acc[i][j] = 0.f;

    // --- load tile 0 ---
    #pragma unroll
    for (int i = 0; i < 2; i++) {
        int r = lr + i * 32;
        float4 v = *(const float4*)(Ap + (size_t)r * HH + lc);
        *(float4*)&As[0][r][lc] = make_float4(tf32r(v.x), tf32r(v.y), tf32r(v.z), tf32r(v.w));
    }
    #pragma unroll
    for (int i = 0; i < 4; i++) {
        int r = lr + i * 32;
        if (r < 104) {
            float4 v = *(const float4*)(V_w + (size_t)r * HH + lc);
            *(float4*)&Bs[0][r][lc] = make_float4(tf32r(v.x), tf32r(v.y), tf32r(v.z), tf32r(v.w));
        }
    }
    __syncthreads();

    const int NT = HH / 16;  // 128
    int buf = 0;

    for (int t = 0; t < NT; t++) {
        float4 ra[2], rb[4];
        if (t + 1 < NT) {
            int k0 = (t + 1) * 16;
            #pragma unroll
            for (int i = 0; i < 2; i++) {
                int r = lr + i * 32;
                ra[i] = *(const float4*)(Ap + (size_t)r * HH + k0 + lc);
            }
            #pragma unroll
            for (int i = 0; i < 4; i++) {
                int r = lr + i * 32;
                rb[i] = (r < 104) ? *(const float4*)(V_w + (size_t)r * HH + k0 + lc)
                                  : make_float4(0.f, 0.f, 0.f, 0.f);
            }
        }

        const float (*Ac)[SKEW] = As[buf];
        const float (*Bc)[SKEW] = Bs[buf];
        #pragma unroll
        for (int kk = 0; kk < 16; kk += 8) {
            unsigned a[4], b[13][2];
            int r0 = wm + grp;
            a[0] = f2u(Ac[r0    ][kk + tig    ]);
            a[1] = f2u(Ac[r0 + 8][kk + tig    ]);
            a[2] = f2u(Ac[r0    ][kk + tig + 4]);
            a[3] = f2u(Ac[r0 + 8][kk + tig + 4]);
            #pragma unroll
            for (int nt = 0; nt < 13; nt++) {
                int c0 = nt * 8 + grp;
                b[nt][0] = f2u(Bc[c0][kk + tig    ]);
                b[nt][1] = f2u(Bc[c0][kk + tig + 4]);
            }
            #pragma unroll
            for (int nt = 0; nt < 13; nt++)
                mma8(acc[nt], a, b[nt]);
        }

        if (t + 1 < NT) {
            float (*An)[SKEW] = As[buf ^ 1];
            float (*Bn)[SKEW] = Bs[buf ^ 1];
            #pragma unroll
            for (int i = 0; i < 2; i++) {
                int r = lr + i * 32;
                *(float4*)&An[r][lc] = make_float4(tf32r(ra[i].x), tf32r(ra[i].y),
                                                   tf32r(ra[i].z), tf32r(ra[i].w));
            }
            #pragma unroll
            for (int i = 0; i < 4; i++) {
                int r = lr + i * 32;
                if (r < 104)
                    *(float4*)&Bn[r][lc] = make_float4(tf32r(rb[i].x), tf32r(rb[i].y),
                                                       tf32r(rb[i].z), tf32r(rb[i].w));
            }
            __syncthreads();
            buf ^= 1;
        }
    }

    // --- epilogue: + V_b, write raw pred (log-softmax in kernel 3) ---
    #pragma unroll
    for (int nt = 0; nt < 13; nt++) {
        int cn = nt * 8 + tig * 2;
        float b0 = V_b[cn], b1 = V_b[cn + 1];
        int rm = mBase + wm + grp;
        *(float2*)&pred[(size_t)rm * DD + cn] =
            make_float2(acc[nt][0] + b0, acc[nt][1] + b1);
        *(float2*)&pred[(size_t)(rm + 8) * DD + cn] =
            make_float2(acc[nt][2] + b0, acc[nt][3] + b1);
    }
}

// ============================================================================
// Kernel 3: segmented log-softmax in place over the 10 fixed column ranges.
// One block per row.
// ============================================================================
__global__ void rnn_k3(float* __restrict__ pred)
{
    __shared__ float row[104];
    __shared__ float seg_m[10], seg_l[10];
    const int b = blockIdx.x;
    float* p = pred + (size_t)b * DD;
    const int t = threadIdx.x;

    if (t < 104) row[t] = p[t];
    __syncthreads();

    if (t < 10) {
        const int bnd[11] = {0, 13, 26, 39, 48, 52, 65, 78, 91, 100, 104};
        int a = bnd[t], e = bnd[t + 1];
        float m = -1e30f;
        for (int j = a; j < e; j++) m = fmaxf(m, row[j]);
        float s = 0.f;
        for (int j = a; j < e; j++) s += expf(row[j] - m);
        seg_m[t] = m;
        seg_l[t] = logf(s);
    }
    __syncthreads();

    if (t < 104) {
        const int bnd[11] = {0, 13, 26, 39, 48, 52, 65, 78, 91, 100, 104};
        int s = 0;
        #pragma unroll
        for (int i = 1; i < 10; i++)
            if (t >= bnd[i]) s = i;
        p[t] = row[t] - seg_m[s] - seg_l[s];
    }
}

// ============================================================================
// Launch: out = [pred_logsoft (8192*104) | h_t (8192*2048)]
// ============================================================================
extern "C" void kernel_launch(void* const* d_in, const int* in_sizes, int n_in,
                              void* d_out, int out_size)
{
    const float* line   = (const float*)d_in[0];
    const float* hidden = (const float*)d_in[1];
    const float* U_w    = (const float*)d_in[2];
    const float* U_b    = (const float*)d_in[3];
    const float* W_w    = (const float*)d_in[4];
    const float* W_b    = (const float*)d_in[5];
    const float* V_w    = (const float*)d_in[6];
    const float* V_b    = (const float*)d_in[7];

    float* out  = (float*)d_out;
    float* pred = out;                          // [8192, 104]
    float* ht   = out + (size_t)BSZ * DD;       // [8192, 2048]

    dim3 g1(HH / 128, BSZ / 128);               // (16, 64)
    rnn_k1<<<g1, 256>>>(hidden, line, U_w, W_w, U_b, W_b, ht);
    rnn_k2<<<BSZ / 64, 128>>>(ht, V_w, V_b, pred);
    rnn_k3<<<BSZ, 128>>>(pred);
}

// round 3
// speedup vs baseline: 1.2095x; 1.2095x over previous
#include <cuda_runtime.h>
#include <cuda_bf16.h>
#include <cstdint>

constexpr int BSZ = 8192;
constexpr int HH  = 2048;
constexpr int DD  = 104;

static __device__ __forceinline__ uint32_t s2u(const void* p) {
    uint32_t a;
    asm("{ .reg .u64 t; cvta.to.shared.u64 t, %1; cvt.u32.u64 %0, t; }"
        : "=r"(a) : "l"(p));
    return a;
}

#define LDSM4(r0, r1, r2, r3, addr)                                          \
    asm volatile("ldmatrix.sync.aligned.m8n8.x4.shared.b16 {%0,%1,%2,%3}, [%4];" \
                 : "=r"(r0), "=r"(r1), "=r"(r2), "=r"(r3) : "r"(addr))

static __device__ __forceinline__ void mma16(float c[4], const uint32_t a[4],
                                             uint32_t b0, uint32_t b1) {
    asm volatile(
        "mma.sync.aligned.m16n8k16.row.col.f32.bf16.bf16.f32 "
        "{%0,%1,%2,%3}, {%4,%5,%6,%7}, {%8,%9}, {%0,%1,%2,%3};\n"
        : "+f"(c[0]), "+f"(c[1]), "+f"(c[2]), "+f"(c[3])
        : "r"(a[0]), "r"(a[1]), "r"(a[2]), "r"(a[3]), "r"(b0), "r"(b1));
}

static __device__ __forceinline__ uint32_t packbf2(float x, float y) {
    __nv_bfloat162 h = __floats2bfloat162_rn(x, y);   // x -> low half
    return *(uint32_t*)&h;
}

static __device__ __forceinline__ float sigmoidf_(float x) {
    return 1.0f / (1.0f + __expf(-x));
}

// ============================================================================
// Kernel 1: h_t = sigmoid(hidden@U_w^T + line@W_w^T + U_b + W_b)
// bf16 mma.sync m16n8k16 + ldmatrix. CTA 128x128, BK=32, 256 thr (2x4 warps,
// 64x32 warp tiles), double-buffered smem with skewed 80B row stride.
// ============================================================================
constexpr int RS = 40;                       // smem row stride in bf16 elems (80B)
constexpr int K1_NT1 = HH / 32;              // 64
constexpr int K1_NT  = K1_NT1 + 4;           // +ceil(104/32) = 68
constexpr int STG_B  = 128 * RS * 2;         // 10240 bytes per operand stage

__global__ __launch_bounds__(256) void rnn_k1(
    const float* __restrict__ hidden, const float* __restrict__ line,
    const float* __restrict__ U_w,    const float* __restrict__ W_w,
    const float* __restrict__ U_b,    const float* __restrict__ W_b,
    float* __restrict__ ht)
{
    __shared__ __align__(16) __nv_bfloat16 As[2][128 * RS];
    __shared__ __align__(16) __nv_bfloat16 Bs[2][128 * RS];
    __shared__ float bias_s[128];

    const int tid  = threadIdx.x;
    const int warp = tid >> 5, lane = tid & 31;
    const int wm   = (warp >> 2) * 64;
    const int wn   = (warp & 3) * 32;
    const int grp  = lane >> 2, tig = lane & 3;
    const int lr16 = lane & 15, lh = lane >> 4;

    const int mBase = blockIdx.y * 128;
    const int nBase = blockIdx.x * 128;

    if (tid < 128) bias_s[tid] = U_b[nBase + tid] + W_b[nBase + tid];

    const uint32_t sbA = s2u(As);
    const uint32_t sbB = s2u(Bs);

    // ldmatrix base offsets (bytes, within one stage)
    uint32_t aOff[4], bOff[2];
    #pragma unroll
    for (int mt = 0; mt < 4; mt++)
        aOff[mt] = ((wm + mt * 16 + lr16) * RS + lh * 8) * 2;
    #pragma unroll
    for (int p = 0; p < 2; p++)
        bOff[p] = ((wn + p * 16 + lr16) * RS + lh * 8) * 2;

    // loader mapping: row = tid>>1 (0..127), col base = (tid&1)*16
    const int lrow = tid >> 1;
    const int lcb  = (tid & 1) * 16;

    const float* pa1 = hidden + (size_t)(mBase + lrow) * HH;
    const float* pb1 = U_w    + (size_t)(nBase + lrow) * HH;
    const float* pa2 = line   + (size_t)(mBase + lrow) * DD;
    const float* pb2 = W_w    + (size_t)(nBase + lrow) * DD;

    float4 pa[4], pb[4];
    auto ldg_tile = [&](int t) {
        if (t < K1_NT1) {
            const float* a = pa1 + t * 32 + lcb;
            const float* b = pb1 + t * 32 + lcb;
            #pragma unroll
            for (int q = 0; q < 4; q++) {
                pa[q] = *(const float4*)(a + q * 4);
                pb[q] = *(const float4*)(b + q * 4);
            }
        } else {
            const int k0 = (t - K1_NT1) * 32;
            #pragma unroll
            for (int q = 0; q < 4; q++) {
                const int c = k0 + lcb + q * 4;
                const bool v = c < DD;                    // DD % 4 == 0
                pa[q] = v ? *(const float4*)(pa2 + c) : make_float4(0.f, 0.f, 0.f, 0.f);
                pb[q] = v ? *(const float4*)(pb2 + c) : make_float4(0.f, 0.f, 0.f, 0.f);
            }
        }
    };
    auto sts_tile = [&](int buf) {
        #pragma unroll
        for (int q = 0; q < 4; q++) {
            const int e = lrow * RS + lcb + q * 4;
            uint2 va = make_uint2(packbf2(pa[q].x, pa[q].y), packbf2(pa[q].z, pa[q].w));
            uint2 vb = make_uint2(packbf2(pb[q].x, pb[q].y), packbf2(pb[q].z, pb[q].w));
            *(uint2*)&As[buf][e] = va;
            *(uint2*)&Bs[buf][e] = vb;
        }
    };

    float acc[4][4][4];
    #pragma unroll
    for (int i = 0; i < 4; i++)
        #pragma unroll
        for (int j = 0; j < 4; j++)
            #pragma unroll
            for (int k = 0; k < 4; k++) acc[i][j][k] = 0.f;

    ldg_tile(0);
    sts_tile(0);
    __syncthreads();

    int buf = 0;
    for (int t = 0; t < K1_NT; t++) {
        if (t + 1 < K1_NT) ldg_tile(t + 1);

        const uint32_t ab = sbA + buf * STG_B;
        const uint32_t bb = sbB + buf * STG_B;
        #pragma unroll
        for (int kk = 0; kk < 32; kk += 16) {
            uint32_t a[4][4], bm[2][4];
            #pragma unroll
            for (int mt = 0; mt < 4; mt++)
                LDSM4(a[mt][0], a[mt][1], a[mt][2], a[mt][3], ab + aOff[mt] + kk * 2);
            #pragma unroll
            for (int p = 0; p < 2; p++)
                LDSM4(bm[p][0], bm[p][1], bm[p][2], bm[p][3], bb + bOff[p] + kk * 2);
            #pragma unroll
            for (int mt = 0; mt < 4; mt++) {
                #pragma unroll
                for (int nt = 0; nt < 4; nt++) {
                    const int p = nt >> 1, o = nt & 1;
                    mma16(acc[mt][nt], a[mt], bm[p][o], bm[p][o + 2]);
                }
            }
        }

        if (t + 1 < K1_NT) {
            __syncthreads();          // everyone done reading buf^1 (prev iter)
            sts_tile(buf ^ 1);
            __syncthreads();
            buf ^= 1;
        }
    }

    // epilogue: bias + sigmoid
    #pragma unroll
    for (int nt = 0; nt < 4; nt++) {
        const int cl = wn + nt * 8 + tig * 2;
        const int cn = nBase + cl;
        const float b0 = bias_s[cl], b1 = bias_s[cl + 1];
        #pragma unroll
        for (int mt = 0; mt < 4; mt++) {
            const int rm = mBase + wm + mt * 16 + grp;
            *(float2*)&ht[(size_t)rm * HH + cn] =
                make_float2(sigmoidf_(acc[mt][nt][0] + b0), sigmoidf_(acc[mt][nt][1] + b1));
            *(float2*)&ht[(size_t)(rm + 8) * HH + cn] =
                make_float2(sigmoidf_(acc[mt][nt][2] + b0), sigmoidf_(acc[mt][nt][3] + b1));
        }
    }
}

// ============================================================================
// Kernel 2: pred = log_softmax_seg(h_t @ V_w^T + V_b)  — fused.
// tf32 mma.sync, 4-stage cp.async, 64x104 tiles, 128 threads.
// ============================================================================
static __device__ __forceinline__ unsigned f2u(float x) { return __float_as_uint(x); }

static __device__ __forceinline__ void mma8(float c[4], const unsigned a[4], const unsigned b[2]) {
    asm volatile(
        "mma.sync.aligned.m16n8k8.row.col.f32.tf32.tf32.f32 "
        "{%0,%1,%2,%3}, {%4,%5,%6,%7}, {%8,%9}, {%0,%1,%2,%3};\n"
        : "+f"(c[0]), "+f"(c[1]), "+f"(c[2]), "+f"(c[3])
        : "r"(a[0]), "r"(a[1]), "r"(a[2]), "r"(a[3]), "r"(b[0]), "r"(b[1]));
}

#define CPA16(dst, src) \
    asm volatile("cp.async.cg.shared.global [%0], [%1], 16;" :: "r"(dst), "l"(src) : "memory")
#define CPA_COMMIT() asm volatile("cp.async.commit_group;" ::: "memory")
#define CPA_WAIT(n)  asm volatile("cp.async.wait_group %0;" :: "n"(n) : "memory")

constexpr int K2_SKEW   = 20;
constexpr int K2_A_B    = 64  * K2_SKEW * 4;          // 5120
constexpr int K2_B_B    = 104 * K2_SKEW * 4;          // 8320
constexpr int K2_STAGE  = K2_A_B + K2_B_B;            // 13440
constexpr int K2_SMEM   = 4 * K2_STAGE;               // 53760

__global__ __launch_bounds__(128) void rnn_k2(
    const float* __restrict__ ht, const float* __restrict__ V_w,
    const float* __restrict__ V_b, float* __restrict__ pred)
{
    extern __shared__ char sm2[];
    const int tid  = threadIdx.x;
    const int warp = tid >> 5, lane = tid & 31;
    const int wm   = warp * 16;
    const int grp  = lane >> 2, tig = lane & 3;

    const int mBase = blockIdx.x * 64;
    const float* Ap = ht + (size_t)mBase * HH;

    float acc[13][4];
    #pragma unroll
    for (int i = 0; i < 13; i++)
        #pragma unroll
        for (int j = 0; j < 4; j++) acc[i][j] = 0.f;

    auto load_stage = [&](int s, int k0) {
        float* Asm = (float*)(sm2 + s * K2_STAGE);
        float* Bsm = (float*)(sm2 + s * K2_STAGE + K2_A_B);
        #pragma unroll
        for (int q = 0; q < 2; q++) {
            int c = tid * 2 + q;
            int row = c >> 2, col = (c & 3) * 4;
            CPA16(s2u(&Asm[row * K2_SKEW + col]), Ap + (size_t)row * HH + k0 + col);
        }
        #pragma unroll
        for (int i = 0; i < 4; i++) {
            int c = tid + i * 128;
            if (c < 416) {
                int row = c >> 2, col = (c & 3) * 4;
                CPA16(s2u(&Bsm[row * K2_SKEW + col]), V_w + (size_t)row * HH + k0 + col);
            }
        }
    };

    #pragma unroll
    for (int s = 0; s < 3; s++) { load_stage(s, s * 16); CPA_COMMIT(); }

    const int NT = HH / 16;  // 128
    for (int t = 0; t < NT; t++) {
        CPA_WAIT(2);
        __syncthreads();

        const int slot = t & 3;
        const float (*Ac)[K2_SKEW] = (const float (*)[K2_SKEW])(sm2 + slot * K2_STAGE);
        const float (*Bc)[K2_SKEW] = (const float (*)[K2_SKEW])(sm2 + slot * K2_STAGE + K2_A_B);
        #pragma unroll
        for (int kk = 0; kk < 16; kk += 8) {
            unsigned a[4], b[13][2];
            int r0 = wm + grp;
            a[0] = f2u(Ac[r0    ][kk + tig    ]);
            a[1] = f2u(Ac[r0 + 8][kk + tig    ]);
            a[2] = f2u(Ac[r0    ][kk + tig + 4]);
            a[3] = f2u(Ac[r0 + 8][kk + tig + 4]);
            #pragma unroll
            for (int nt = 0; nt < 13; nt++) {
                int c0 = nt * 8 + grp;
                b[nt][0] = f2u(Bc[c0][kk + tig    ]);
                b[nt][1] = f2u(Bc[c0][kk + tig + 4]);
            }
            #pragma unroll
            for (int nt = 0; nt < 13; nt++) mma8(acc[nt], a, b[nt]);
        }
        __syncthreads();
        if (t + 3 < NT) load_stage((t + 3) & 3, (t + 3) * 16);
        CPA_COMMIT();
    }

    // -------- fused epilogue: bias + segmented log-softmax ------------------
    __syncthreads();                     // pipeline smem now dead; reuse it
    float* st   = (float*)sm2;           // [64][108]
    float* segm = st + 64 * 108;         // [64][10]
    float* segl = segm + 640;            // [64][10]

    #pragma unroll
    for (int nt = 0; nt < 13; nt++) {
        const int cn = nt * 8 + tig * 2;
        const float b0 = V_b[cn], b1 = V_b[cn + 1];
        const int r = wm + grp;
        st[r * 108 + cn]           = acc[nt][0] + b0;
        st[r * 108 + cn + 1]       = acc[nt][1] + b1;
        st[(r + 8) * 108 + cn]     = acc[nt][2] + b0;
        st[(r + 8) * 108 + cn + 1] = acc[nt][3] + b1;
    }
    __syncthreads();

    const int bnd[11] = {0, 13, 26, 39, 48, 52, 65, 78, 91, 100, 104};
    if (tid < 64) {
        const float* row = st + tid * 108;
        #pragma unroll
        for (int s = 0; s < 10; s++) {
            float m = -1e30f;
            for (int j = bnd[s]; j < bnd[s + 1]; j++) m = fmaxf(m, row[j]);
            float sum = 0.f;
            for (int j = bnd[s]; j < bnd[s + 1]; j++) sum += expf(row[j] - m);
            segm[tid * 10 + s] = m;
            segl[tid * 10 + s] = logf(sum);
        }
    }
    __syncthreads();

    if (tid < 104) {
        int sg = 0;
        #pragma unroll
        for (int i = 1; i < 10; i++)
            if (tid >= bnd[i]) sg = i;
        for (int r = 0; r < 64; r++) {
            pred[(size_t)(mBase + r) * DD + tid] =
                st[r * 108 + tid] - segm[r * 10 + sg] - segl[r * 10 + sg];
        }
    }
}

// ============================================================================
// Launch: out = [pred_logsoft (8192*104) | h_t (8192*2048)]
// ============================================================================
extern "C" void kernel_launch(void* const* d_in, const int* in_sizes, int n_in,
                              void* d_out, int out_size)
{
    const float* line   = (const float*)d_in[0];
    const float* hidden = (const float*)d_in[1];
    const float* U_w    = (const float*)d_in[2];
    const float* U_b    = (const float*)d_in[3];
    const float* W_w    = (const float*)d_in[4];
    const float* W_b    = (const float*)d_in[5];
    const float* V_w    = (const float*)d_in[6];
    const float* V_b    = (const float*)d_in[7];

    float* out  = (float*)d_out;
    float* pred = out;                          // [8192, 104]
    float* ht   = out + (size_t)BSZ * DD;       // [8192, 2048]

    static bool attr_set = false;
    if (!attr_set) {
        cudaFuncSetAttribute(rnn_k2, cudaFuncAttributeMaxDynamicSharedMemorySize, K2_SMEM);
        attr_set = true;
    }

    dim3 g1(HH / 128, BSZ / 128);               // (16, 64)
    rnn_k1<<<g1, 256>>>(hidden, line, U_w, W_w, U_b, W_b, ht);
    rnn_k2<<<BSZ / 64, 128, K2_SMEM>>>(ht, V_w, V_b, pred);
}

// round 4
// speedup vs baseline: 1.6371x; 1.3536x over previous
#include <cuda_runtime.h>
#include <cuda_bf16.h>
#include <cstdint>

constexpr int BSZ = 8192;
constexpr int HH  = 2048;
constexpr int DD  = 104;
constexpr int DP  = 128;                      // padded D for uniform K loop

// bf16 scratch (device globals: allowed; no dynamic allocation)
__device__ __nv_bfloat16 g_hid[(size_t)BSZ * HH];    // 33.5 MB
__device__ __nv_bfloat16 g_Uw [(size_t)HH  * HH];    //  8.4 MB
__device__ __nv_bfloat16 g_line[(size_t)BSZ * DP];   //  2.1 MB (zero-padded)
__device__ __nv_bfloat16 g_Ww [(size_t)HH  * DP];    //  0.5 MB (zero-padded)

static __device__ __forceinline__ uint32_t s2u(const void* p) {
    uint32_t a;
    asm("{ .reg .u64 t; cvta.to.shared.u64 t, %1; cvt.u32.u64 %0, t; }"
        : "=r"(a) : "l"(p));
    return a;
}

#define LDSM4(r0, r1, r2, r3, addr)                                          \
    asm volatile("ldmatrix.sync.aligned.m8n8.x4.shared.b16 {%0,%1,%2,%3}, [%4];" \
                 : "=r"(r0), "=r"(r1), "=r"(r2), "=r"(r3) : "r"(addr))

static __device__ __forceinline__ void mma16(float c[4], const uint32_t a[4],
                                             uint32_t b0, uint32_t b1) {
    asm volatile(
        "mma.sync.aligned.m16n8k16.row.col.f32.bf16.bf16.f32 "
        "{%0,%1,%2,%3}, {%4,%5,%6,%7}, {%8,%9}, {%0,%1,%2,%3};\n"
        : "+f"(c[0]), "+f"(c[1]), "+f"(c[2]), "+f"(c[3])
        : "r"(a[0]), "r"(a[1]), "r"(a[2]), "r"(a[3]), "r"(b0), "r"(b1));
}

#define CPA16(dst, src) \
    asm volatile("cp.async.cg.shared.global [%0], [%1], 16;" :: "r"(dst), "l"(src) : "memory")
#define CPA_COMMIT() asm volatile("cp.async.commit_group;" ::: "memory")
#define CPA_WAIT(n)  asm volatile("cp.async.wait_group %0;" :: "n"(n) : "memory")

static __device__ __forceinline__ float sigmoidf_(float x) {
    return 1.0f / (1.0f + __expf(-x));
}

// ============================================================================
// k0a: fp32 -> bf16 bulk convert (hidden then U_w), float4 granularity
// ============================================================================
constexpr size_t NH4 = (size_t)BSZ * HH / 4;   // 4194304
constexpr size_t NU4 = (size_t)HH  * HH / 4;   // 1048576

__global__ __launch_bounds__(256) void cvt_main(const float4* __restrict__ hid,
                                                const float4* __restrict__ uw)
{
    size_t i = (size_t)blockIdx.x * blockDim.x + threadIdx.x;
    if (i >= NH4 + NU4) return;
    float4 v; __nv_bfloat16* dst;
    if (i < NH4) { v = hid[i];        dst = g_hid + i * 4; }
    else         { v = uw[i - NH4];   dst = g_Uw  + (i - NH4) * 4; }
    uint2 o;
    __nv_bfloat162 lo = __floats2bfloat162_rn(v.x, v.y);
    __nv_bfloat162 hi = __floats2bfloat162_rn(v.z, v.w);
    o.x = *(uint32_t*)&lo; o.y = *(uint32_t*)&hi;
    *(uint2*)dst = o;
}

// k0b: line + W_w -> zero-padded bf16 [*, 128]
__global__ __launch_bounds__(256) void cvt_pad(const float* __restrict__ line,
                                               const float* __restrict__ ww)
{
    size_t i = (size_t)blockIdx.x * blockDim.x + threadIdx.x;
    const size_t TOT = (size_t)(BSZ + HH) * DP;
    if (i >= TOT) return;
    size_t row = i >> 7;
    int    col = (int)(i & 127);
    float v = 0.f;
    if (col < DD)
        v = (row < BSZ) ? line[row * DD + col] : ww[(row - BSZ) * DD + col];
    ((row < BSZ) ? g_line : g_Ww)[((row < BSZ) ? row : row - BSZ) * DP + col] =
        __float2bfloat16(v);
}

// ============================================================================
// Kernel 1: h_t = sigmoid(hidden@U_w^T + line@W_w^T + U_b + W_b)
// bf16 m16n8k16 + ldmatrix + 4-stage cp.async. CTA 128x128, BK=32, 256 thr.
// ============================================================================
constexpr int RS      = 40;                   // smem row stride, bf16 elems (80B)
constexpr int OP_B    = 128 * RS * 2;         // 10240 B per operand per stage
constexpr int STG     = 2 * OP_B;             // 20480 B per stage
constexpr int K1_ST   = 4;
constexpr int K1_SMEM = K1_ST * STG;          // 81920
constexpr int K1_NT   = HH / 32 + DP / 32;    // 64 + 4 = 68
constexpr int K1_NT1  = HH / 32;

__global__ __launch_bounds__(256) void rnn_k1(
    const float* __restrict__ U_b, const float* __restrict__ W_b,
    float* __restrict__ ht)
{
    extern __shared__ char sm1[];
    const uint32_t sb = s2u(sm1);

    const int tid  = threadIdx.x;
    const int warp = tid >> 5, lane = tid & 31;
    const int wm   = (warp >> 2) * 64;
    const int wn   = (warp & 3) * 32;
    const int grp  = lane >> 2, tig = lane & 3;
    const int lr16 = lane & 15, lh = lane >> 4;

    const int mBase = blockIdx.y * 128;
    const int nBase = blockIdx.x * 128;

    // ldmatrix byte offsets within a stage's operand region
    uint32_t aOff[4], bOff[2];
    #pragma unroll
    for (int mt = 0; mt < 4; mt++)
        aOff[mt] = ((wm + mt * 16 + lr16) * RS + lh * 8) * 2;
    #pragma unroll
    for (int p = 0; p < 2; p++)
        bOff[p] = ((wn + p * 16 + lr16) * RS + lh * 8) * 2;

    // producer: thread owns row tid>>1, 32B chunk pair at col (tid&1)*16
    const int lrow = tid >> 1;
    const int lcb  = (tid & 1) * 16;
    const __nv_bfloat16* hA = g_hid  + (size_t)(mBase + lrow) * HH + lcb;
    const __nv_bfloat16* uB = g_Uw   + (size_t)(nBase + lrow) * HH + lcb;
    const __nv_bfloat16* lA = g_line + (size_t)(mBase + lrow) * DP + lcb;
    const __nv_bfloat16* wB = g_Ww   + (size_t)(nBase + lrow) * DP + lcb;
    const uint32_t dOff = (uint32_t)(lrow * RS + lcb) * 2;

    auto issue_stage = [&](int slot, int f) {
        const uint32_t dA = sb + slot * STG + dOff;
        const uint32_t dB = dA + OP_B;
        const __nv_bfloat16 *sA, *sB;
        if (f < K1_NT1) { sA = hA + f * 32;             sB = uB + f * 32; }
        else            { sA = lA + (f - K1_NT1) * 32;  sB = wB + (f - K1_NT1) * 32; }
        CPA16(dA,      sA);
        CPA16(dA + 16, sA + 8);
        CPA16(dB,      sB);
        CPA16(dB + 16, sB + 8);
    };

    float acc[4][4][4];
    #pragma unroll
    for (int i = 0; i < 4; i++)
        #pragma unroll
        for (int j = 0; j < 4; j++)
            #pragma unroll
            for (int k = 0; k < 4; k++) acc[i][j][k] = 0.f;

    #pragma unroll
    for (int s = 0; s < K1_ST - 1; s++) { issue_stage(s, s); CPA_COMMIT(); }

    for (int t = 0; t < K1_NT; t++) {
        CPA_WAIT(2);
        __syncthreads();

        const int slot = t & (K1_ST - 1);
        const uint32_t ab = sb + slot * STG;
        const uint32_t bb = ab + OP_B;
        #pragma unroll
        for (int kk = 0; kk < 32; kk += 16) {
            uint32_t a[4][4], bm[2][4];
            #pragma unroll
            for (int mt = 0; mt < 4; mt++)
                LDSM4(a[mt][0], a[mt][1], a[mt][2], a[mt][3], ab + aOff[mt] + kk * 2);
            #pragma unroll
            for (int p = 0; p < 2; p++)
                LDSM4(bm[p][0], bm[p][1], bm[p][2], bm[p][3], bb + bOff[p] + kk * 2);
            #pragma unroll
            for (int mt = 0; mt < 4; mt++) {
                #pragma unroll
                for (int nt = 0; nt < 4; nt++) {
                    const int p = nt >> 1, o = nt & 1;
                    mma16(acc[mt][nt], a[mt], bm[p][o], bm[p][o + 2]);
                }
            }
        }
        __syncthreads();                 // all reads of this slot done before refill
        if (t + K1_ST - 1 < K1_NT) issue_stage((t + K1_ST - 1) & (K1_ST - 1), t + K1_ST - 1);
        CPA_COMMIT();                    // commit every iter (possibly empty)
    }

    // epilogue: bias + sigmoid -> fp32 h_t
    #pragma unroll
    for (int nt = 0; nt < 4; nt++) {
        const int cn = nBase + wn + nt * 8 + tig * 2;
        const float b0 = U_b[cn]     + W_b[cn];
        const float b1 = U_b[cn + 1] + W_b[cn + 1];
        #pragma unroll
        for (int mt = 0; mt < 4; mt++) {
            const int rm = mBase + wm + mt * 16 + grp;
            *(float2*)&ht[(size_t)rm * HH + cn] =
                make_float2(sigmoidf_(acc[mt][nt][0] + b0), sigmoidf_(acc[mt][nt][1] + b1));
            *(float2*)&ht[(size_t)(rm + 8) * HH + cn] =
                make_float2(sigmoidf_(acc[mt][nt][2] + b0), sigmoidf_(acc[mt][nt][3] + b1));
        }
    }
}

// ============================================================================
// Kernel 2: pred = log_softmax_seg(h_t @ V_w^T + V_b), fused.
// tf32 mma, 4-stage cp.async, M=32 per CTA (grid 256), 128 threads / 4 warps.
// Warp layout: (warp&1)->M half, (warp>>1)->N tiles 0..6 / 7..12.
// ============================================================================
static __device__ __forceinline__ unsigned f2u(float x) { return __float_as_uint(x); }

static __device__ __forceinline__ void mma8(float c[4], const unsigned a[4], const unsigned b[2]) {
    asm volatile(
        "mma.sync.aligned.m16n8k8.row.col.f32.tf32.tf32.f32 "
        "{%0,%1,%2,%3}, {%4,%5,%6,%7}, {%8,%9}, {%0,%1,%2,%3};\n"
        : "+f"(c[0]), "+f"(c[1]), "+f"(c[2]), "+f"(c[3])
        : "r"(a[0]), "r"(a[1]), "r"(a[2]), "r"(a[3]), "r"(b[0]), "r"(b[1]));
}

constexpr int K2_SKEW  = 20;
constexpr int K2_A_B   = 32  * K2_SKEW * 4;           // 2560
constexpr int K2_B_B   = 104 * K2_SKEW * 4;           // 8320
constexpr int K2_STAGE = K2_A_B + K2_B_B;             // 10880
constexpr int K2_SMEM  = 4 * K2_STAGE;                // 43520

__global__ __launch_bounds__(128) void rnn_k2(
    const float* __restrict__ ht, const float* __restrict__ V_w,
    const float* __restrict__ V_b, float* __restrict__ pred)
{
    extern __shared__ char sm2[];
    const int tid  = threadIdx.x;
    const int warp = tid >> 5, lane = tid & 31;
    const int wm   = (warp & 1) * 16;
    const int nh   = warp >> 1;                  // 0: tiles 0..6, 1: tiles 7..12
    const int ntn  = 7 - nh;                     // 7 or 6
    const int grp  = lane >> 2, tig = lane & 3;

    const int mBase = blockIdx.x * 32;
    const float* Ap = ht + (size_t)mBase * HH;

    float acc[7][4];
    #pragma unroll
    for (int i = 0; i < 7; i++)
        #pragma unroll
        for (int j = 0; j < 4; j++) acc[i][j] = 0.f;

    auto load_stage = [&](int s, int k0) {
        float* Asm = (float*)(sm2 + s * K2_STAGE);
        float* Bsm = (float*)(sm2 + s * K2_STAGE + K2_A_B);
        {   // A: 32 rows x 4 chunks = 128 = tid
            int row = tid >> 2, col = (tid & 3) * 4;
            CPA16(s2u(&Asm[row * K2_SKEW + col]), Ap + (size_t)row * HH + k0 + col);
        }
        #pragma unroll
        for (int i = 0; i < 4; i++) {            // B: 104 x 4 = 416 chunks
            int c = tid + i * 128;
            if (c < 416) {
                int row = c >> 2, col = (c & 3) * 4;
                CPA16(s2u(&Bsm[row * K2_SKEW + col]), V_w + (size_t)row * HH + k0 + col);
            }
        }
    };

    #pragma unroll
    for (int s = 0; s < 3; s++) { load_stage(s, s * 16); CPA_COMMIT(); }

    const int NT = HH / 16;  // 128
    for (int t = 0; t < NT; t++) {
        CPA_WAIT(2);
        __syncthreads();

        const int slot = t & 3;
        const float (*Ac)[K2_SKEW] = (const float (*)[K2_SKEW])(sm2 + slot * K2_STAGE);
        const float (*Bc)[K2_SKEW] = (const float (*)[K2_SKEW])(sm2 + slot * K2_STAGE + K2_A_B);
        #pragma unroll
        for (int kk = 0; kk < 16; kk += 8) {
            unsigned a[4], b[7][2];
            const int r0 = wm + grp;
            a[0] = f2u(Ac[r0    ][kk + tig    ]);
            a[1] = f2u(Ac[r0 + 8][kk + tig    ]);
            a[2] = f2u(Ac[r0    ][kk + tig + 4]);
            a[3] = f2u(Ac[r0 + 8][kk + tig + 4]);
            #pragma unroll
            for (int nt = 0; nt < 7; nt++) {
                if (nt < ntn) {
                    const int c0 = (nh * 7 + nt) * 8 + grp;
                    b[nt][0] = f2u(Bc[c0][kk + tig    ]);
                    b[nt][1] = f2u(Bc[c0][kk + tig + 4]);
                }
            }
            #pragma unroll
            for (int nt = 0; nt < 7; nt++)
                if (nt < ntn) mma8(acc[nt], a, b[nt]);
        }
        __syncthreads();
        if (t + 3 < NT) load_stage((t + 3) & 3, (t + 3) * 16);
        CPA_COMMIT();
    }

    // -------- fused epilogue: bias + segmented log-softmax ------------------
    __syncthreads();
    float* st   = (float*)sm2;            // [32][108]
    float* segm = st + 32 * 108;          // [32][10]
    float* segl = segm + 320;             // [32][10]

    #pragma unroll
    for (int nt = 0; nt < 7; nt++) {
        if (nt < ntn) {
            const int cn = (nh * 7 + nt) * 8 + tig * 2;
            const float b0 = V_b[cn], b1 = V_b[cn + 1];
            const int r = wm + grp;
            st[r * 108 + cn]           = acc[nt][0] + b0;
            st[r * 108 + cn + 1]       = acc[nt][1] + b1;
            st[(r + 8) * 108 + cn]     = acc[nt][2] + b0;
            st[(r + 8) * 108 + cn + 1] = acc[nt][3] + b1;
        }
    }
    __syncthreads();

    const int bnd[11] = {0, 13, 26, 39, 48, 52, 65, 78, 91, 100, 104};
    if (tid < 32) {
        const float* row = st + tid * 108;
        #pragma unroll
        for (int s = 0; s < 10; s++) {
            float m = -1e30f;
            for (int j = bnd[s]; j < bnd[s + 1]; j++) m = fmaxf(m, row[j]);
            float sum = 0.f;
            for (int j = bnd[s]; j < bnd[s + 1]; j++) sum += expf(row[j] - m);
            segm[tid * 10 + s] = m;
            segl[tid * 10 + s] = logf(sum);
        }
    }
    __syncthreads();

    if (tid < 104) {
        int sg = 0;
        #pragma unroll
        for (int i = 1; i < 10; i++)
            if (tid >= bnd[i]) sg = i;
        for (int r = 0; r < 32; r++)
            pred[(size_t)(mBase + r) * DD + tid] =
                st[r * 108 + tid] - segm[r * 10 + sg] - segl[r * 10 + sg];
    }
}

// ============================================================================
// Launch: out = [pred_logsoft (8192*104) | h_t (8192*2048)]
// ============================================================================
extern "C" void kernel_launch(void* const* d_in, const int* in_sizes, int n_in,
                              void* d_out, int out_size)
{
    const float* line   = (const float*)d_in[0];
    const float* hidden = (const float*)d_in[1];
    const float* U_w    = (const float*)d_in[2];
    const float* U_b    = (const float*)d_in[3];
    const float* W_w    = (const float*)d_in[4];
    const float* W_b    = (const float*)d_in[5];
    const float* V_w    = (const float*)d_in[6];
    const float* V_b    = (const float*)d_in[7];

    float* out  = (float*)d_out;
    float* pred = out;                          // [8192, 104]
    float* ht   = out + (size_t)BSZ * DD;       // [8192, 2048]

    cudaFuncSetAttribute(rnn_k1, cudaFuncAttributeMaxDynamicSharedMemorySize, K1_SMEM);
    cudaFuncSetAttribute(rnn_k2, cudaFuncAttributeMaxDynamicSharedMemorySize, K2_SMEM);

    const int gc = (int)((NH4 + NU4 + 255) / 256);
    cvt_main<<<gc, 256>>>((const float4*)hidden, (const float4*)U_w);
    const int gp = (int)(((size_t)(BSZ + HH) * DP + 255) / 256);
    cvt_pad<<<gp, 256>>>(line, W_w);

    dim3 g1(HH / 128, BSZ / 128);               // (16, 64)
    rnn_k1<<<g1, 256, K1_SMEM>>>(U_b, W_b, ht);
    rnn_k2<<<BSZ / 32, 128, K2_SMEM>>>(ht, V_w, V_b, pred);
}

// round 5
// speedup vs baseline: 1.7755x; 1.0845x over previous
#include <cuda_runtime.h>
#include <cuda_bf16.h>
#include <cstdint>

constexpr int BSZ = 8192;
constexpr int HH  = 2048;
constexpr int DD  = 104;
constexpr int DP  = 128;                      // padded D for uniform K loop

// bf16 scratch (device globals — no dynamic allocation)
__device__ __nv_bfloat16 g_hid[(size_t)BSZ * HH];    // 33.5 MB
__device__ __nv_bfloat16 g_Uw [(size_t)HH  * HH];    //  8.4 MB
__device__ __nv_bfloat16 g_line[(size_t)BSZ * DP];   //  2.1 MB (zero-padded)
__device__ __nv_bfloat16 g_Ww [(size_t)HH  * DP];    //  0.5 MB (zero-padded)
__device__ __nv_bfloat16 g_htb[(size_t)BSZ * HH];    // 33.5 MB (h_t in bf16)
__device__ __nv_bfloat16 g_Vwb[(size_t)DD  * HH];    //  0.4 MB

static __device__ __forceinline__ uint32_t s2u(const void* p) {
    uint32_t a;
    asm("{ .reg .u64 t; cvta.to.shared.u64 t, %1; cvt.u32.u64 %0, t; }"
        : "=r"(a) : "l"(p));
    return a;
}

#define LDSM4(r0, r1, r2, r3, addr)                                          \
    asm volatile("ldmatrix.sync.aligned.m8n8.x4.shared.b16 {%0,%1,%2,%3}, [%4];" \
                 : "=r"(r0), "=r"(r1), "=r"(r2), "=r"(r3) : "r"(addr))

static __device__ __forceinline__ void mma16(float c[4], const uint32_t a[4],
                                             uint32_t b0, uint32_t b1) {
    asm volatile(
        "mma.sync.aligned.m16n8k16.row.col.f32.bf16.bf16.f32 "
        "{%0,%1,%2,%3}, {%4,%5,%6,%7}, {%8,%9}, {%0,%1,%2,%3};\n"
        : "+f"(c[0]), "+f"(c[1]), "+f"(c[2]), "+f"(c[3])
        : "r"(a[0]), "r"(a[1]), "r"(a[2]), "r"(a[3]), "r"(b0), "r"(b1));
}

#define CPA16(dst, src) \
    asm volatile("cp.async.cg.shared.global [%0], [%1], 16;" :: "r"(dst), "l"(src) : "memory")
#define CPA_COMMIT() asm volatile("cp.async.commit_group;" ::: "memory")
#define CPA_WAIT(n)  asm volatile("cp.async.wait_group %0;" :: "n"(n) : "memory")

static __device__ __forceinline__ float sigmoidf_(float x) {
    return 1.0f / (1.0f + __expf(-x));
}
static __device__ __forceinline__ uint32_t packbf2(float x, float y) {
    __nv_bfloat162 h = __floats2bfloat162_rn(x, y);
    return *(uint32_t*)&h;
}

// ============================================================================
// converts
// ============================================================================
constexpr size_t NH4 = (size_t)BSZ * HH / 4;
constexpr size_t NU4 = (size_t)HH  * HH / 4;

__global__ __launch_bounds__(256) void cvt_main(const float4* __restrict__ hid,
                                                const float4* __restrict__ uw)
{
    size_t i = (size_t)blockIdx.x * blockDim.x + threadIdx.x;
    if (i >= NH4 + NU4) return;
    float4 v; __nv_bfloat16* dst;
    if (i < NH4) { v = hid[i];      dst = g_hid + i * 4; }
    else         { v = uw[i - NH4]; dst = g_Uw  + (i - NH4) * 4; }
    uint2 o;
    o.x = packbf2(v.x, v.y);
    o.y = packbf2(v.z, v.w);
    *(uint2*)dst = o;
}

__global__ __launch_bounds__(256) void cvt_pad(const float* __restrict__ line,
                                               const float* __restrict__ ww)
{
    size_t i = (size_t)blockIdx.x * blockDim.x + threadIdx.x;
    const size_t TOT = (size_t)(BSZ + HH) * DP;
    if (i >= TOT) return;
    size_t row = i >> 7;
    int    col = (int)(i & 127);
    float v = 0.f;
    if (col < DD)
        v = (row < BSZ) ? line[row * DD + col] : ww[(row - BSZ) * DD + col];
    ((row < BSZ) ? g_line : g_Ww)[((row < BSZ) ? row : row - BSZ) * DP + col] =
        __float2bfloat16(v);
}

constexpr size_t NV4 = (size_t)DD * HH / 4;   // 53248
__global__ __launch_bounds__(256) void cvt_vw(const float4* __restrict__ vw)
{
    size_t i = (size_t)blockIdx.x * blockDim.x + threadIdx.x;
    if (i >= NV4) return;
    float4 v = vw[i];
    uint2 o;
    o.x = packbf2(v.x, v.y);
    o.y = packbf2(v.z, v.w);
    *(uint2*)(g_Vwb + i * 4) = o;
}

// ============================================================================
// Kernel 1: h_t = sigmoid(hidden@U_w^T + line@W_w^T + U_b + W_b)
// bf16 m16n8k16 + ldmatrix + 4-stage cp.async, single barrier per iter.
// CTA 128x128, BK=32, 256 thr. Writes h_t fp32 (output) + bf16 (scratch).
// ============================================================================
constexpr int RS      = 40;                   // smem row stride, bf16 elems (80B)
constexpr int OP_B    = 128 * RS * 2;         // 10240 B
constexpr int STG     = 2 * OP_B;             // 20480 B
constexpr int K1_ST   = 4;
constexpr int K1_SMEM = K1_ST * STG;          // 81920
constexpr int K1_NT1  = HH / 32;              // 64
constexpr int K1_NT   = K1_NT1 + DP / 32;     // 68

__global__ __launch_bounds__(256) void rnn_k1(
    const float* __restrict__ U_b, const float* __restrict__ W_b,
    float* __restrict__ ht)
{
    extern __shared__ char sm1[];
    const uint32_t sb = s2u(sm1);

    const int tid  = threadIdx.x;
    const int warp = tid >> 5, lane = tid & 31;
    const int wm   = (warp >> 2) * 64;
    const int wn   = (warp & 3) * 32;
    const int grp  = lane >> 2, tig = lane & 3;
    const int lr16 = lane & 15, lh = lane >> 4;

    const int mBase = blockIdx.y * 128;
    const int nBase = blockIdx.x * 128;

    uint32_t aOff[4], bOff[2];
    #pragma unroll
    for (int mt = 0; mt < 4; mt++)
        aOff[mt] = ((wm + mt * 16 + lr16) * RS + lh * 8) * 2;
    #pragma unroll
    for (int p = 0; p < 2; p++)
        bOff[p] = ((wn + p * 16 + lr16) * RS + lh * 8) * 2;

    const int lrow = tid >> 1;
    const int lcb  = (tid & 1) * 16;
    const __nv_bfloat16* hA = g_hid  + (size_t)(mBase + lrow) * HH + lcb;
    const __nv_bfloat16* uB = g_Uw   + (size_t)(nBase + lrow) * HH + lcb;
    const __nv_bfloat16* lA = g_line + (size_t)(mBase + lrow) * DP + lcb;
    const __nv_bfloat16* wB = g_Ww   + (size_t)(nBase + lrow) * DP + lcb;
    const uint32_t dOff = (uint32_t)(lrow * RS + lcb) * 2;

    auto issue_stage = [&](int slot, int f) {
        const uint32_t dA = sb + slot * STG + dOff;
        const uint32_t dB = dA + OP_B;
        const __nv_bfloat16 *sA, *sB;
        if (f < K1_NT1) { sA = hA + f * 32;             sB = uB + f * 32; }
        else            { sA = lA + (f - K1_NT1) * 32;  sB = wB + (f - K1_NT1) * 32; }
        CPA16(dA,      sA);
        CPA16(dA + 16, sA + 8);
        CPA16(dB,      sB);
        CPA16(dB + 16, sB + 8);
    };

    float acc[4][4][4];
    #pragma unroll
    for (int i = 0; i < 4; i++)
        #pragma unroll
        for (int j = 0; j < 4; j++)
            #pragma unroll
            for (int k = 0; k < 4; k++) acc[i][j][k] = 0.f;

    #pragma unroll
    for (int s = 0; s < K1_ST - 1; s++) { issue_stage(s, s); CPA_COMMIT(); }

    for (int t = 0; t < K1_NT; t++) {
        CPA_WAIT(2);
        __syncthreads();
        // refill slot (t+3)&3 == (t-1)&3: last read in iter t-1, all threads
        // are past that compute (they reached this barrier). Safe.
        if (t + K1_ST - 1 < K1_NT)
            issue_stage((t + K1_ST - 1) & (K1_ST - 1), t + K1_ST - 1);
        CPA_COMMIT();

        const int slot = t & (K1_ST - 1);
        const uint32_t ab = sb + slot * STG;
        const uint32_t bb = ab + OP_B;
        #pragma unroll
        for (int kk = 0; kk < 32; kk += 16) {
            uint32_t a[4][4], bm[2][4];
            #pragma unroll
            for (int mt = 0; mt < 4; mt++)
                LDSM4(a[mt][0], a[mt][1], a[mt][2], a[mt][3], ab + aOff[mt] + kk * 2);
            #pragma unroll
            for (int p = 0; p < 2; p++)
                LDSM4(bm[p][0], bm[p][1], bm[p][2], bm[p][3], bb + bOff[p] + kk * 2);
            #pragma unroll
            for (int mt = 0; mt < 4; mt++) {
                #pragma unroll
                for (int nt = 0; nt < 4; nt++) {
                    const int p = nt >> 1, o = nt & 1;
                    mma16(acc[mt][nt], a[mt], bm[p][o], bm[p][o + 2]);
                }
            }
        }
    }

    // epilogue: bias + sigmoid -> fp32 h_t (output) + bf16 h_t (scratch)
    #pragma unroll
    for (int nt = 0; nt < 4; nt++) {
        const int cn = nBase + wn + nt * 8 + tig * 2;
        const float b0 = U_b[cn]     + W_b[cn];
        const float b1 = U_b[cn + 1] + W_b[cn + 1];
        #pragma unroll
        for (int mt = 0; mt < 4; mt++) {
            const int rm = mBase + wm + mt * 16 + grp;
            const float s00 = sigmoidf_(acc[mt][nt][0] + b0);
            const float s01 = sigmoidf_(acc[mt][nt][1] + b1);
            const float s10 = sigmoidf_(acc[mt][nt][2] + b0);
            const float s11 = sigmoidf_(acc[mt][nt][3] + b1);
            *(float2*)&ht[(size_t)rm * HH + cn]       = make_float2(s00, s01);
            *(float2*)&ht[(size_t)(rm + 8) * HH + cn] = make_float2(s10, s11);
            *(uint32_t*)&g_htb[(size_t)rm * HH + cn]       = packbf2(s00, s01);
            *(uint32_t*)&g_htb[(size_t)(rm + 8) * HH + cn] = packbf2(s10, s11);
        }
    }
}

// ============================================================================
// Kernel 2: pred = log_softmax_seg(h_t @ V_w^T + V_b), fused. ALL bf16.
// M=32/CTA (grid 256), 128 threads. BK=32 bf16, 64 iters, 4-stage cp.async.
// Warp layout: (warp&1)->M half, (warp>>1)->N tiles 0..6 / 7..12.
// ============================================================================
constexpr int RS2      = 40;                      // bf16 elems per smem row (80B)
constexpr int K2_A_B   = 32  * RS2 * 2;           // 2560 B
constexpr int K2_B_B   = 104 * RS2 * 2;           // 8320 B
constexpr int K2_STAGE = K2_A_B + K2_B_B;         // 10880
constexpr int K2_SMEM  = 4 * K2_STAGE;            // 43520
constexpr int K2_NT    = HH / 32;                 // 64

__global__ __launch_bounds__(128) void rnn_k2(
    const float* __restrict__ V_b, float* __restrict__ pred)
{
    extern __shared__ char sm2[];
    const uint32_t sb = s2u(sm2);
    const int tid  = threadIdx.x;
    const int warp = tid >> 5, lane = tid & 31;
    const int wm   = (warp & 1) * 16;
    const int nh   = warp >> 1;
    const int ntn  = 7 - nh;                 // 7 or 6 n8-tiles
    const int grp  = lane >> 2, tig = lane & 3;

    const int mBase = blockIdx.x * 32;
    const __nv_bfloat16* Ap = g_htb + (size_t)mBase * HH;

    float acc[7][4];
    #pragma unroll
    for (int i = 0; i < 7; i++)
        #pragma unroll
        for (int j = 0; j < 4; j++) acc[i][j] = 0.f;

    // A chunk per thread: row tid>>2, 16B chunk (tid&3); B: 416 chunks
    auto load_stage = [&](int s, int k0) {
        const uint32_t base = sb + s * K2_STAGE;
        {
            const int row = tid >> 2, cc = (tid & 3) * 8;  // 8 bf16 per chunk
            CPA16(base + (uint32_t)(row * RS2 + cc) * 2,
                  Ap + (size_t)row * HH + k0 + cc);
        }
        #pragma unroll
        for (int i = 0; i < 4; i++) {
            const int c = tid + i * 128;
            if (c < 416) {
                const int row = c >> 2, cc = (c & 3) * 8;
                CPA16(base + K2_A_B + (uint32_t)(row * RS2 + cc) * 2,
                      g_Vwb + (size_t)row * HH + k0 + cc);
            }
        }
    };

    #pragma unroll
    for (int s = 0; s < 3; s++) { load_stage(s, s * 32); CPA_COMMIT(); }

    for (int t = 0; t < K2_NT; t++) {
        CPA_WAIT(2);
        __syncthreads();
        if (t + 3 < K2_NT) load_stage((t + 3) & 3, (t + 3) * 32);
        CPA_COMMIT();

        const int slot = t & 3;
        const __nv_bfloat16* As = (const __nv_bfloat16*)(sm2 + slot * K2_STAGE);
        const __nv_bfloat16* Bs = (const __nv_bfloat16*)(sm2 + slot * K2_STAGE + K2_A_B);
        #pragma unroll
        for (int kk = 0; kk < 32; kk += 16) {
            uint32_t a[4];
            const int r0 = wm + grp;
            a[0] = *(const uint32_t*)&As[r0 * RS2 + kk + 2 * tig];
            a[1] = *(const uint32_t*)&As[(r0 + 8) * RS2 + kk + 2 * tig];
            a[2] = *(const uint32_t*)&As[r0 * RS2 + kk + 2 * tig + 8];
            a[3] = *(const uint32_t*)&As[(r0 + 8) * RS2 + kk + 2 * tig + 8];
            #pragma unroll
            for (int nt = 0; nt < 7; nt++) {
                if (nt < ntn) {
                    const int c0 = (nh * 7 + nt) * 8 + grp;
                    const uint32_t blo = *(const uint32_t*)&Bs[c0 * RS2 + kk + 2 * tig];
                    const uint32_t bhi = *(const uint32_t*)&Bs[c0 * RS2 + kk + 2 * tig + 8];
                    mma16(acc[nt], a, blo, bhi);
                }
            }
        }
    }

    // -------- fused epilogue: bias + segmented log-softmax ------------------
    __syncthreads();
    float* st   = (float*)sm2;            // [32][108]
    float* segm = st + 32 * 108;
    float* segl = segm + 320;

    #pragma unroll
    for (int nt = 0; nt < 7; nt++) {
        if (nt < ntn) {
            const int cn = (nh * 7 + nt) * 8 + tig * 2;
            const float b0 = V_b[cn], b1 = V_b[cn + 1];
            const int r = wm + grp;
            st[r * 108 + cn]           = acc[nt][0] + b0;
            st[r * 108 + cn + 1]       = acc[nt][1] + b1;
            st[(r + 8) * 108 + cn]     = acc[nt][2] + b0;
            st[(r + 8) * 108 + cn + 1] = acc[nt][3] + b1;
        }
    }
    __syncthreads();

    const int bnd[11] = {0, 13, 26, 39, 48, 52, 65, 78, 91, 100, 104};
    if (tid < 32) {
        const float* row = st + tid * 108;
        #pragma unroll
        for (int s = 0; s < 10; s++) {
            float m = -1e30f;
            for (int j = bnd[s]; j < bnd[s + 1]; j++) m = fmaxf(m, row[j]);
            float sum = 0.f;
            for (int j = bnd[s]; j < bnd[s + 1]; j++) sum += expf(row[j] - m);
            segm[tid * 10 + s] = m;
            segl[tid * 10 + s] = logf(sum);
        }
    }
    __syncthreads();

    if (tid < 104) {
        int sg = 0;
        #pragma unroll
        for (int i = 1; i < 10; i++)
            if (tid >= bnd[i]) sg = i;
        for (int r = 0; r < 32; r++)
            pred[(size_t)(mBase + r) * DD + tid] =
                st[r * 108 + tid] - segm[r * 10 + sg] - segl[r * 10 + sg];
    }
}

// ============================================================================
// Launch
// ============================================================================
extern "C" void kernel_launch(void* const* d_in, const int* in_sizes, int n_in,
                              void* d_out, int out_size)
{
    const float* line   = (const float*)d_in[0];
    const float* hidden = (const float*)d_in[1];
    const float* U_w    = (const float*)d_in[2];
    const float* U_b    = (const float*)d_in[3];
    const float* W_w    = (const float*)d_in[4];
    const float* W_b    = (const float*)d_in[5];
    const float* V_w    = (const float*)d_in[6];
    const float* V_b    = (const float*)d_in[7];

    float* out  = (float*)d_out;
    float* pred = out;                          // [8192, 104]
    float* ht   = out + (size_t)BSZ * DD;       // [8192, 2048]

    cudaFuncSetAttribute(rnn_k1, cudaFuncAttributeMaxDynamicSharedMemorySize, K1_SMEM);
    cudaFuncSetAttribute(rnn_k2, cudaFuncAttributeMaxDynamicSharedMemorySize, K2_SMEM);

    const int gc = (int)((NH4 + NU4 + 255) / 256);
    cvt_main<<<gc, 256>>>((const float4*)hidden, (const float4*)U_w);
    const int gp = (int)(((size_t)(BSZ + HH) * DP + 255) / 256);
    cvt_pad<<<gp, 256>>>(line, W_w);
    cvt_vw<<<(int)((NV4 + 255) / 256), 256>>>((const float4*)V_w);

    dim3 g1(HH / 128, BSZ / 128);               // (16, 64)
    rnn_k1<<<g1, 256, K1_SMEM>>>(U_b, W_b, ht);
    rnn_k2<<<BSZ / 32, 128, K2_SMEM>>>(V_b, pred);
}